// round 8
// baseline (speedup 1.0000x reference)
#include <cuda_runtime.h>

#define B_  8
#define N_  1024
#define C_  1024
#define H_  16
#define HD_ 64
#define QKV_COLS (3 * C_)   // 3072

// Scratch (allocation-free: device globals)
__device__ float g_qkv[(size_t)B_ * N_ * QKV_COLS];  // [B*N, 3072]
__device__ float g_ao [(size_t)B_ * N_ * C_];        // [B*N, 1024] (b,n,h,hd)

// ---------------------------------------------------------------------------
// NT SGEMM: C[M,Nn] = A[M,K] @ B[Nn,K]^T (+ bias[Nn])
// 128x128 tile, BK=16, 256 threads, 8x8 per-thread fragments.
// ---------------------------------------------------------------------------
template <bool BIAS>
__global__ __launch_bounds__(256)
void sgemm_nt(const float* __restrict__ A, const float* __restrict__ Bm,
              const float* __restrict__ bias, float* __restrict__ Cc,
              int M, int Nn, int K)
{
    __shared__ float As[16][132];
    __shared__ float Bs[16][132];

    const int tid = threadIdx.x;
    const int tx = tid & 15;          // 0..15 -> col group
    const int ty = tid >> 4;          // 0..15 -> row group
    const int m0 = blockIdx.y * 128;
    const int n0 = blockIdx.x * 128;

    float acc[8][8];
#pragma unroll
    for (int i = 0; i < 8; ++i)
#pragma unroll
        for (int j = 0; j < 8; ++j) acc[i][j] = 0.f;

    for (int kt = 0; kt < K; kt += 16) {
#pragma unroll
        for (int it = 0; it < 2; ++it) {
            int e   = tid + it * 256;        // 0..511
            int row = e >> 2;                // 0..127
            int kc  = (e & 3) << 2;          // 0,4,8,12
            float4 va = *(const float4*)(A  + (size_t)(m0 + row) * K + kt + kc);
            As[kc + 0][row] = va.x; As[kc + 1][row] = va.y;
            As[kc + 2][row] = va.z; As[kc + 3][row] = va.w;
            float4 vb = *(const float4*)(Bm + (size_t)(n0 + row) * K + kt + kc);
            Bs[kc + 0][row] = vb.x; Bs[kc + 1][row] = vb.y;
            Bs[kc + 2][row] = vb.z; Bs[kc + 3][row] = vb.w;
        }
        __syncthreads();

#pragma unroll
        for (int k = 0; k < 16; ++k) {
            float a[8], b[8];
            *(float4*)(a)     = *(const float4*)&As[k][ty * 8];
            *(float4*)(a + 4) = *(const float4*)&As[k][ty * 8 + 4];
            *(float4*)(b)     = *(const float4*)&Bs[k][tx * 8];
            *(float4*)(b + 4) = *(const float4*)&Bs[k][tx * 8 + 4];
#pragma unroll
            for (int i = 0; i < 8; ++i)
#pragma unroll
                for (int j = 0; j < 8; ++j)
                    acc[i][j] = fmaf(a[i], b[j], acc[i][j]);
        }
        __syncthreads();
    }

#pragma unroll
    for (int i = 0; i < 8; ++i) {
        float* crow = Cc + (size_t)(m0 + ty * 8 + i) * Nn + n0 + tx * 8;
#pragma unroll
        for (int j = 0; j < 8; ++j) {
            float v = acc[i][j];
            if (BIAS) v += bias[n0 + tx * 8 + j];
            crow[j] = v;
        }
    }
}

// ---------------------------------------------------------------------------
// Flash attention: one block = (b,h) x 64-query tile, loops 16 key tiles of 64.
// Dynamic smem: Qs[64][68] (d-major, pre-scaled), Ks[64][68] (d-major),
//               Vs[64][64] (m-major), Ps[64][68] (P staging for P@V).
// ---------------------------------------------------------------------------
#define QSS 68
#define ATTN_SMEM_FLOATS (64 * QSS * 3 + 64 * 64)
#define ATTN_SMEM_BYTES  (ATTN_SMEM_FLOATS * 4)

__global__ __launch_bounds__(256)
void attn_kernel(const float* __restrict__ qkv, float* __restrict__ ao)
{
    extern __shared__ float sm[];
    float* Qs = sm;
    float* Ks = sm + 64 * QSS;
    float* Vs = sm + 2 * 64 * QSS;
    float* Ps = sm + 2 * 64 * QSS + 64 * 64;

    const int tid = threadIdx.x;
    const int tx = tid & 15;      // key-col / d-col group (4 wide)
    const int ty = tid >> 4;      // query-row group (4 wide)
    const int bh = blockIdx.x;
    const int b  = bh >> 4;
    const int h  = bh & 15;
    const int r0 = blockIdx.y * 64;
    const float scale = 0.125f;   // HD^-0.5

    const float* qb = qkv + (size_t)b * N_ * QKV_COLS + h * HD_;

    // Load Q tile transposed (Qs[d][r]), pre-scaled
#pragma unroll
    for (int it = 0; it < 4; ++it) {
        int e = tid + it * 256;          // 0..1023
        int r = e >> 4;                  // 0..63
        int d = (e & 15) << 2;           // 0..60
        float4 v = *(const float4*)(qb + (size_t)(r0 + r) * QKV_COLS + d);
        Qs[(d + 0) * QSS + r] = v.x * scale;
        Qs[(d + 1) * QSS + r] = v.y * scale;
        Qs[(d + 2) * QSS + r] = v.z * scale;
        Qs[(d + 3) * QSS + r] = v.w * scale;
    }

    float mrow[4], lrow[4], o[4][4];
#pragma unroll
    for (int i = 0; i < 4; ++i) {
        mrow[i] = -1e30f; lrow[i] = 0.f;
#pragma unroll
        for (int j = 0; j < 4; ++j) o[i][j] = 0.f;
    }

    for (int t = 0; t < 16; ++t) {
        __syncthreads();   // previous P@V done before overwriting K/V/P tiles

        // Load K (transposed, d-major) and V (m-major) tiles
#pragma unroll
        for (int it = 0; it < 4; ++it) {
            int e = tid + it * 256;
            int m = e >> 4;
            int d = (e & 15) << 2;
            const float* kb = qkv + (size_t)(b * N_ + t * 64 + m) * QKV_COLS
                              + C_ + h * HD_ + d;
            float4 kv = *(const float4*)kb;
            Ks[(d + 0) * QSS + m] = kv.x;
            Ks[(d + 1) * QSS + m] = kv.y;
            Ks[(d + 2) * QSS + m] = kv.z;
            Ks[(d + 3) * QSS + m] = kv.w;
            float4 vv = *(const float4*)(kb + C_);
            *(float4*)&Vs[m * 64 + d] = vv;
        }
        __syncthreads();

        // S = (Q*scale) @ K^T, 4x4 fragment per thread
        float s[4][4];
#pragma unroll
        for (int i = 0; i < 4; ++i)
#pragma unroll
            for (int j = 0; j < 4; ++j) s[i][j] = 0.f;

#pragma unroll 8
        for (int d = 0; d < 64; ++d) {
            float a[4], bb[4];
            *(float4*)a  = *(const float4*)&Qs[d * QSS + ty * 4];
            *(float4*)bb = *(const float4*)&Ks[d * QSS + tx * 4];
#pragma unroll
            for (int i = 0; i < 4; ++i)
#pragma unroll
                for (int j = 0; j < 4; ++j)
                    s[i][j] = fmaf(a[i], bb[j], s[i][j]);
        }

        // Online softmax (row stats reduced across the 16 tx lanes)
#pragma unroll
        for (int i = 0; i < 4; ++i) {
            float rm = fmaxf(fmaxf(s[i][0], s[i][1]), fmaxf(s[i][2], s[i][3]));
#pragma unroll
            for (int off = 8; off >= 1; off >>= 1)
                rm = fmaxf(rm, __shfl_xor_sync(0xffffffffu, rm, off));
            float mnew  = fmaxf(mrow[i], rm);
            float alpha = __expf(mrow[i] - mnew);
            float rs = 0.f;
#pragma unroll
            for (int j = 0; j < 4; ++j) {
                s[i][j] = __expf(s[i][j] - mnew);
                rs += s[i][j];
            }
#pragma unroll
            for (int off = 8; off >= 1; off >>= 1)
                rs += __shfl_xor_sync(0xffffffffu, rs, off);
            lrow[i] = lrow[i] * alpha + rs;
            mrow[i] = mnew;
#pragma unroll
            for (int j = 0; j < 4; ++j) o[i][j] *= alpha;
            *(float4*)&Ps[(ty * 4 + i) * QSS + tx * 4] =
                make_float4(s[i][0], s[i][1], s[i][2], s[i][3]);
        }
        __syncthreads();

        // O += P @ V  (o fragment cols are d-cols tx*4..+3)
#pragma unroll 8
        for (int m = 0; m < 64; ++m) {
            float bb[4];
            *(float4*)bb = *(const float4*)&Vs[m * 64 + tx * 4];
#pragma unroll
            for (int i = 0; i < 4; ++i) {
                float av = Ps[(ty * 4 + i) * QSS + m];
#pragma unroll
                for (int j = 0; j < 4; ++j)
                    o[i][j] = fmaf(av, bb[j], o[i][j]);
            }
        }
    }

    // Epilogue: O / l -> [b, n, h, hd] layout for out-proj
#pragma unroll
    for (int i = 0; i < 4; ++i) {
        float inv = 1.f / lrow[i];
        int r = r0 + ty * 4 + i;
        float4 v = make_float4(o[i][0] * inv, o[i][1] * inv,
                               o[i][2] * inv, o[i][3] * inv);
        *(float4*)(ao + (size_t)(b * N_ + r) * C_ + h * HD_ + tx * 4) = v;
    }
}

// ---------------------------------------------------------------------------
extern "C" void kernel_launch(void* const* d_in, const int* in_sizes, int n_in,
                              void* d_out, int out_size)
{
    const float* x      = (const float*)d_in[0];
    const float* w_qkv  = (const float*)d_in[1];
    const float* w_proj = (const float*)d_in[2];
    const float* b_proj = (const float*)d_in[3];
    float* out = (float*)d_out;

    float *qkv, *ao;
    cudaGetSymbolAddress((void**)&qkv, g_qkv);
    cudaGetSymbolAddress((void**)&ao,  g_ao);

    // 1) QKV projection: [8192,1024] @ [3072,1024]^T
    sgemm_nt<false><<<dim3(QKV_COLS / 128, (B_ * N_) / 128), 256>>>(
        x, w_qkv, nullptr, qkv, B_ * N_, QKV_COLS, C_);

    // 2) Flash attention
    cudaFuncSetAttribute(attn_kernel,
                         cudaFuncAttributeMaxDynamicSharedMemorySize,
                         ATTN_SMEM_BYTES);
    attn_kernel<<<dim3(B_ * H_, N_ / 64), 256, ATTN_SMEM_BYTES>>>(qkv, ao);

    // 3) Output projection + bias: [8192,1024] @ [1024,1024]^T + b
    sgemm_nt<true><<<dim3(C_ / 128, (B_ * N_) / 128), 256>>>(
        ao, w_proj, b_proj, out, B_ * N_, C_, C_);
}

// round 9
// speedup vs baseline: 1.0003x; 1.0003x over previous
#include <cuda_runtime.h>

#define B_  8
#define N_  1024
#define C_  1024
#define H_  16
#define HD_ 64
#define QKV_COLS (3 * C_)   // 3072

// Scratch (allocation-free: device globals)
__device__ float g_qkv[(size_t)B_ * N_ * QKV_COLS];  // [B*N, 3072]
__device__ float g_ao [(size_t)B_ * N_ * C_];        // [B*N, 1024] (b,n,h,hd)

// ---------------------------------------------------------------------------
// NT SGEMM: C[M,Nn] = A[M,K] @ B[Nn,K]^T (+ bias[Nn])
// 128x128 tile, BK=16, 256 threads, 8x8 per-thread fragments.
// ---------------------------------------------------------------------------
template <bool BIAS>
__global__ __launch_bounds__(256)
void sgemm_nt(const float* __restrict__ A, const float* __restrict__ Bm,
              const float* __restrict__ bias, float* __restrict__ Cc,
              int M, int Nn, int K)
{
    __shared__ float As[16][132];
    __shared__ float Bs[16][132];

    const int tid = threadIdx.x;
    const int tx = tid & 15;          // 0..15 -> col group
    const int ty = tid >> 4;          // 0..15 -> row group
    const int m0 = blockIdx.y * 128;
    const int n0 = blockIdx.x * 128;

    float acc[8][8];
#pragma unroll
    for (int i = 0; i < 8; ++i)
#pragma unroll
        for (int j = 0; j < 8; ++j) acc[i][j] = 0.f;

    for (int kt = 0; kt < K; kt += 16) {
#pragma unroll
        for (int it = 0; it < 2; ++it) {
            int e   = tid + it * 256;        // 0..511
            int row = e >> 2;                // 0..127
            int kc  = (e & 3) << 2;          // 0,4,8,12
            float4 va = *(const float4*)(A  + (size_t)(m0 + row) * K + kt + kc);
            As[kc + 0][row] = va.x; As[kc + 1][row] = va.y;
            As[kc + 2][row] = va.z; As[kc + 3][row] = va.w;
            float4 vb = *(const float4*)(Bm + (size_t)(n0 + row) * K + kt + kc);
            Bs[kc + 0][row] = vb.x; Bs[kc + 1][row] = vb.y;
            Bs[kc + 2][row] = vb.z; Bs[kc + 3][row] = vb.w;
        }
        __syncthreads();

#pragma unroll
        for (int k = 0; k < 16; ++k) {
            float a[8], b[8];
            *(float4*)(a)     = *(const float4*)&As[k][ty * 8];
            *(float4*)(a + 4) = *(const float4*)&As[k][ty * 8 + 4];
            *(float4*)(b)     = *(const float4*)&Bs[k][tx * 8];
            *(float4*)(b + 4) = *(const float4*)&Bs[k][tx * 8 + 4];
#pragma unroll
            for (int i = 0; i < 8; ++i)
#pragma unroll
                for (int j = 0; j < 8; ++j)
                    acc[i][j] = fmaf(a[i], b[j], acc[i][j]);
        }
        __syncthreads();
    }

#pragma unroll
    for (int i = 0; i < 8; ++i) {
        float* crow = Cc + (size_t)(m0 + ty * 8 + i) * Nn + n0 + tx * 8;
#pragma unroll
        for (int j = 0; j < 8; ++j) {
            float v = acc[i][j];
            if (BIAS) v += bias[n0 + tx * 8 + j];
            crow[j] = v;
        }
    }
}

// ---------------------------------------------------------------------------
// Flash attention: one block = (b,h) x 64-query tile, loops 16 key tiles of 64.
// Dynamic smem: Qs[64][68] (d-major, pre-scaled), Ks[64][68] (d-major),
//               Vs[64][64] (m-major), Ps[64][68] (P staging for P@V).
// ---------------------------------------------------------------------------
#define QSS 68
#define ATTN_SMEM_FLOATS (64 * QSS * 3 + 64 * 64)
#define ATTN_SMEM_BYTES  (ATTN_SMEM_FLOATS * 4)

__global__ __launch_bounds__(256)
void attn_kernel(const float* __restrict__ qkv, float* __restrict__ ao)
{
    extern __shared__ float sm[];
    float* Qs = sm;
    float* Ks = sm + 64 * QSS;
    float* Vs = sm + 2 * 64 * QSS;
    float* Ps = sm + 2 * 64 * QSS + 64 * 64;

    const int tid = threadIdx.x;
    const int tx = tid & 15;      // key-col / d-col group (4 wide)
    const int ty = tid >> 4;      // query-row group (4 wide)
    const int bh = blockIdx.x;
    const int b  = bh >> 4;
    const int h  = bh & 15;
    const int r0 = blockIdx.y * 64;
    const float scale = 0.125f;   // HD^-0.5

    const float* qb = qkv + (size_t)b * N_ * QKV_COLS + h * HD_;

    // Load Q tile transposed (Qs[d][r]), pre-scaled
#pragma unroll
    for (int it = 0; it < 4; ++it) {
        int e = tid + it * 256;          // 0..1023
        int r = e >> 4;                  // 0..63
        int d = (e & 15) << 2;           // 0..60
        float4 v = *(const float4*)(qb + (size_t)(r0 + r) * QKV_COLS + d);
        Qs[(d + 0) * QSS + r] = v.x * scale;
        Qs[(d + 1) * QSS + r] = v.y * scale;
        Qs[(d + 2) * QSS + r] = v.z * scale;
        Qs[(d + 3) * QSS + r] = v.w * scale;
    }

    float mrow[4], lrow[4], o[4][4];
#pragma unroll
    for (int i = 0; i < 4; ++i) {
        mrow[i] = -1e30f; lrow[i] = 0.f;
#pragma unroll
        for (int j = 0; j < 4; ++j) o[i][j] = 0.f;
    }

    for (int t = 0; t < 16; ++t) {
        __syncthreads();   // previous P@V done before overwriting K/V/P tiles

        // Load K (transposed, d-major) and V (m-major) tiles
#pragma unroll
        for (int it = 0; it < 4; ++it) {
            int e = tid + it * 256;
            int m = e >> 4;
            int d = (e & 15) << 2;
            const float* kb = qkv + (size_t)(b * N_ + t * 64 + m) * QKV_COLS
                              + C_ + h * HD_ + d;
            float4 kv = *(const float4*)kb;
            Ks[(d + 0) * QSS + m] = kv.x;
            Ks[(d + 1) * QSS + m] = kv.y;
            Ks[(d + 2) * QSS + m] = kv.z;
            Ks[(d + 3) * QSS + m] = kv.w;
            float4 vv = *(const float4*)(kb + C_);
            *(float4*)&Vs[m * 64 + d] = vv;
        }
        __syncthreads();

        // S = (Q*scale) @ K^T, 4x4 fragment per thread
        float s[4][4];
#pragma unroll
        for (int i = 0; i < 4; ++i)
#pragma unroll
            for (int j = 0; j < 4; ++j) s[i][j] = 0.f;

#pragma unroll 8
        for (int d = 0; d < 64; ++d) {
            float a[4], bb[4];
            *(float4*)a  = *(const float4*)&Qs[d * QSS + ty * 4];
            *(float4*)bb = *(const float4*)&Ks[d * QSS + tx * 4];
#pragma unroll
            for (int i = 0; i < 4; ++i)
#pragma unroll
                for (int j = 0; j < 4; ++j)
                    s[i][j] = fmaf(a[i], bb[j], s[i][j]);
        }

        // Online softmax (row stats reduced across the 16 tx lanes)
#pragma unroll
        for (int i = 0; i < 4; ++i) {
            float rm = fmaxf(fmaxf(s[i][0], s[i][1]), fmaxf(s[i][2], s[i][3]));
#pragma unroll
            for (int off = 8; off >= 1; off >>= 1)
                rm = fmaxf(rm, __shfl_xor_sync(0xffffffffu, rm, off));
            float mnew  = fmaxf(mrow[i], rm);
            float alpha = __expf(mrow[i] - mnew);
            float rs = 0.f;
#pragma unroll
            for (int j = 0; j < 4; ++j) {
                s[i][j] = __expf(s[i][j] - mnew);
                rs += s[i][j];
            }
#pragma unroll
            for (int off = 8; off >= 1; off >>= 1)
                rs += __shfl_xor_sync(0xffffffffu, rs, off);
            lrow[i] = lrow[i] * alpha + rs;
            mrow[i] = mnew;
#pragma unroll
            for (int j = 0; j < 4; ++j) o[i][j] *= alpha;
            *(float4*)&Ps[(ty * 4 + i) * QSS + tx * 4] =
                make_float4(s[i][0], s[i][1], s[i][2], s[i][3]);
        }
        __syncthreads();

        // O += P @ V  (o fragment cols are d-cols tx*4..+3)
#pragma unroll 8
        for (int m = 0; m < 64; ++m) {
            float bb[4];
            *(float4*)bb = *(const float4*)&Vs[m * 64 + tx * 4];
#pragma unroll
            for (int i = 0; i < 4; ++i) {
                float av = Ps[(ty * 4 + i) * QSS + m];
#pragma unroll
                for (int j = 0; j < 4; ++j)
                    o[i][j] = fmaf(av, bb[j], o[i][j]);
            }
        }
    }

    // Epilogue: O / l -> [b, n, h, hd] layout for out-proj
#pragma unroll
    for (int i = 0; i < 4; ++i) {
        float inv = 1.f / lrow[i];
        int r = r0 + ty * 4 + i;
        float4 v = make_float4(o[i][0] * inv, o[i][1] * inv,
                               o[i][2] * inv, o[i][3] * inv);
        *(float4*)(ao + (size_t)(b * N_ + r) * C_ + h * HD_ + tx * 4) = v;
    }
}

// ---------------------------------------------------------------------------
extern "C" void kernel_launch(void* const* d_in, const int* in_sizes, int n_in,
                              void* d_out, int out_size)
{
    const float* x      = (const float*)d_in[0];
    const float* w_qkv  = (const float*)d_in[1];
    const float* w_proj = (const float*)d_in[2];
    const float* b_proj = (const float*)d_in[3];
    float* out = (float*)d_out;

    float *qkv, *ao;
    cudaGetSymbolAddress((void**)&qkv, g_qkv);
    cudaGetSymbolAddress((void**)&ao,  g_ao);

    // 1) QKV projection: [8192,1024] @ [3072,1024]^T
    sgemm_nt<false><<<dim3(QKV_COLS / 128, (B_ * N_) / 128), 256>>>(
        x, w_qkv, nullptr, qkv, B_ * N_, QKV_COLS, C_);

    // 2) Flash attention
    cudaFuncSetAttribute(attn_kernel,
                         cudaFuncAttributeMaxDynamicSharedMemorySize,
                         ATTN_SMEM_BYTES);
    attn_kernel<<<dim3(B_ * H_, N_ / 64), 256, ATTN_SMEM_BYTES>>>(qkv, ao);

    // 3) Output projection + bias: [8192,1024] @ [1024,1024]^T + b
    sgemm_nt<true><<<dim3(C_ / 128, (B_ * N_) / 128), 256>>>(
        ao, w_proj, b_proj, out, B_ * N_, C_, C_);
}

// round 10
// speedup vs baseline: 1.7188x; 1.7182x over previous
#include <cuda_runtime.h>
#include <cstdint>

#define B_  8
#define N_  1024
#define C_  1024
#define H_  16
#define HD_ 64
#define QKV_COLS (3 * C_)   // 3072

// Scratch (allocation-free: device globals)
__device__ float g_qkv[(size_t)B_ * N_ * QKV_COLS];  // [B*N, 3072]
__device__ float g_ao [(size_t)B_ * N_ * C_];        // [B*N, 1024] (b,n,h,hd)

// ---------------------------------------------------------------------------
// TF32 tensor-core NT GEMM: C[M,Nn] = A[M,K] @ B[Nn,K]^T (+ bias[Nn])
// 128x128x32 tiles, 256 threads (8 warps, 2x4 grid -> 64x32 warp tile),
// mma.sync.m16n8k8.tf32, fp32 accumulate. Smem stride 36 words -> the
// fragment-load bank pattern (4g+c)&31 is conflict-free.
// ---------------------------------------------------------------------------
__device__ __forceinline__ uint32_t f2tf32(float x) {
    uint32_t u;
    asm("cvt.rna.tf32.f32 %0, %1;" : "=r"(u) : "f"(x));
    return u;
}

__device__ __forceinline__ void mma_tf32(float* d, const uint32_t* a,
                                         const uint32_t* b) {
    asm volatile(
        "mma.sync.aligned.m16n8k8.row.col.f32.tf32.tf32.f32 "
        "{%0,%1,%2,%3}, {%4,%5,%6,%7}, {%8,%9}, {%0,%1,%2,%3};"
        : "+f"(d[0]), "+f"(d[1]), "+f"(d[2]), "+f"(d[3])
        : "r"(a[0]), "r"(a[1]), "r"(a[2]), "r"(a[3]),
          "r"(b[0]), "r"(b[1]));
}

#define SSTR 36   // smem row stride in words (conflict-free fragment loads)

template <bool BIAS>
__global__ __launch_bounds__(256, 2)
void tf32_gemm_nt(const float* __restrict__ A, const float* __restrict__ Bm,
                  const float* __restrict__ bias, float* __restrict__ Cc,
                  int M, int Nn, int K)
{
    __shared__ uint32_t As[128][SSTR];   // [m][k]
    __shared__ uint32_t Bs[128][SSTR];   // [n][k]

    const int tid  = threadIdx.x;
    const int lane = tid & 31;
    const int w    = tid >> 5;            // 0..7
    const int wm   = (w >> 2) * 64;       // warp m offset (0 or 64)
    const int wn   = (w & 3) * 32;        // warp n offset (0..96)
    const int g    = lane >> 2;           // 0..7
    const int c4   = lane & 3;            // 0..3
    const int m0   = blockIdx.y * 128;
    const int n0   = blockIdx.x * 128;

    // gmem tile-load coords: 256 threads x 4 iters cover 128x32 in float4
    const int lrow = tid >> 3;            // 0..31 (+32 per iter)
    const int lcol = (tid & 7) * 4;       // 0,4,...,28

    float d[4][4][4];
#pragma unroll
    for (int i = 0; i < 4; ++i)
#pragma unroll
        for (int j = 0; j < 4; ++j)
#pragma unroll
            for (int r = 0; r < 4; ++r) d[i][j][r] = 0.f;

    for (int kt = 0; kt < K; kt += 32) {
#pragma unroll
        for (int it = 0; it < 4; ++it) {
            int row = lrow + it * 32;
            float4 va = *(const float4*)(A  + (size_t)(m0 + row) * K + kt + lcol);
            uint4 ta;
            ta.x = f2tf32(va.x); ta.y = f2tf32(va.y);
            ta.z = f2tf32(va.z); ta.w = f2tf32(va.w);
            *(uint4*)&As[row][lcol] = ta;
            float4 vb = *(const float4*)(Bm + (size_t)(n0 + row) * K + kt + lcol);
            uint4 tb;
            tb.x = f2tf32(vb.x); tb.y = f2tf32(vb.y);
            tb.z = f2tf32(vb.z); tb.w = f2tf32(vb.w);
            *(uint4*)&Bs[row][lcol] = tb;
        }
        __syncthreads();

#pragma unroll
        for (int kk = 0; kk < 32; kk += 8) {
            uint32_t af[4][4], bf[4][2];
#pragma unroll
            for (int i = 0; i < 4; ++i) {
                int mr = wm + i * 16 + g;
                af[i][0] = As[mr    ][kk + c4];
                af[i][1] = As[mr + 8][kk + c4];
                af[i][2] = As[mr    ][kk + c4 + 4];
                af[i][3] = As[mr + 8][kk + c4 + 4];
            }
#pragma unroll
            for (int j = 0; j < 4; ++j) {
                int nr = wn + j * 8 + g;
                bf[j][0] = Bs[nr][kk + c4];
                bf[j][1] = Bs[nr][kk + c4 + 4];
            }
#pragma unroll
            for (int i = 0; i < 4; ++i)
#pragma unroll
                for (int j = 0; j < 4; ++j)
                    mma_tf32(d[i][j], af[i], bf[j]);
        }
        __syncthreads();
    }

    // Epilogue: c0 (g, c4*2), c1 (+1), c2 (g+8, c4*2), c3 (+1)
#pragma unroll
    for (int i = 0; i < 4; ++i) {
        int row = m0 + wm + i * 16 + g;
#pragma unroll
        for (int j = 0; j < 4; ++j) {
            int col = n0 + wn + j * 8 + c4 * 2;
            float b0 = 0.f, b1 = 0.f;
            if (BIAS) { b0 = bias[col]; b1 = bias[col + 1]; }
            *(float2*)(Cc + (size_t)row * Nn + col) =
                make_float2(d[i][j][0] + b0, d[i][j][1] + b1);
            *(float2*)(Cc + (size_t)(row + 8) * Nn + col) =
                make_float2(d[i][j][2] + b0, d[i][j][3] + b1);
        }
    }
}

// ---------------------------------------------------------------------------
// Flash attention (unchanged fp32): one block = (b,h) x 64-query tile.
// ---------------------------------------------------------------------------
#define QSS 68
#define ATTN_SMEM_FLOATS (64 * QSS * 3 + 64 * 64)
#define ATTN_SMEM_BYTES  (ATTN_SMEM_FLOATS * 4)

__global__ __launch_bounds__(256)
void attn_kernel(const float* __restrict__ qkv, float* __restrict__ ao)
{
    extern __shared__ float sm[];
    float* Qs = sm;
    float* Ks = sm + 64 * QSS;
    float* Vs = sm + 2 * 64 * QSS;
    float* Ps = sm + 2 * 64 * QSS + 64 * 64;

    const int tid = threadIdx.x;
    const int tx = tid & 15;
    const int ty = tid >> 4;
    const int bh = blockIdx.x;
    const int b  = bh >> 4;
    const int h  = bh & 15;
    const int r0 = blockIdx.y * 64;
    const float scale = 0.125f;

    const float* qb = qkv + (size_t)b * N_ * QKV_COLS + h * HD_;

#pragma unroll
    for (int it = 0; it < 4; ++it) {
        int e = tid + it * 256;
        int r = e >> 4;
        int dd = (e & 15) << 2;
        float4 v = *(const float4*)(qb + (size_t)(r0 + r) * QKV_COLS + dd);
        Qs[(dd + 0) * QSS + r] = v.x * scale;
        Qs[(dd + 1) * QSS + r] = v.y * scale;
        Qs[(dd + 2) * QSS + r] = v.z * scale;
        Qs[(dd + 3) * QSS + r] = v.w * scale;
    }

    float mrow[4], lrow[4], o[4][4];
#pragma unroll
    for (int i = 0; i < 4; ++i) {
        mrow[i] = -1e30f; lrow[i] = 0.f;
#pragma unroll
        for (int j = 0; j < 4; ++j) o[i][j] = 0.f;
    }

    for (int t = 0; t < 16; ++t) {
        __syncthreads();

#pragma unroll
        for (int it = 0; it < 4; ++it) {
            int e = tid + it * 256;
            int m = e >> 4;
            int dd = (e & 15) << 2;
            const float* kb = qkv + (size_t)(b * N_ + t * 64 + m) * QKV_COLS
                              + C_ + h * HD_ + dd;
            float4 kv = *(const float4*)kb;
            Ks[(dd + 0) * QSS + m] = kv.x;
            Ks[(dd + 1) * QSS + m] = kv.y;
            Ks[(dd + 2) * QSS + m] = kv.z;
            Ks[(dd + 3) * QSS + m] = kv.w;
            float4 vv = *(const float4*)(kb + C_);
            *(float4*)&Vs[m * 64 + dd] = vv;
        }
        __syncthreads();

        float s[4][4];
#pragma unroll
        for (int i = 0; i < 4; ++i)
#pragma unroll
            for (int j = 0; j < 4; ++j) s[i][j] = 0.f;

#pragma unroll 8
        for (int dd = 0; dd < 64; ++dd) {
            float a[4], bb[4];
            *(float4*)a  = *(const float4*)&Qs[dd * QSS + ty * 4];
            *(float4*)bb = *(const float4*)&Ks[dd * QSS + tx * 4];
#pragma unroll
            for (int i = 0; i < 4; ++i)
#pragma unroll
                for (int j = 0; j < 4; ++j)
                    s[i][j] = fmaf(a[i], bb[j], s[i][j]);
        }

#pragma unroll
        for (int i = 0; i < 4; ++i) {
            float rm = fmaxf(fmaxf(s[i][0], s[i][1]), fmaxf(s[i][2], s[i][3]));
#pragma unroll
            for (int off = 8; off >= 1; off >>= 1)
                rm = fmaxf(rm, __shfl_xor_sync(0xffffffffu, rm, off));
            float mnew  = fmaxf(mrow[i], rm);
            float alpha = __expf(mrow[i] - mnew);
            float rs = 0.f;
#pragma unroll
            for (int j = 0; j < 4; ++j) {
                s[i][j] = __expf(s[i][j] - mnew);
                rs += s[i][j];
            }
#pragma unroll
            for (int off = 8; off >= 1; off >>= 1)
                rs += __shfl_xor_sync(0xffffffffu, rs, off);
            lrow[i] = lrow[i] * alpha + rs;
            mrow[i] = mnew;
#pragma unroll
            for (int j = 0; j < 4; ++j) o[i][j] *= alpha;
            *(float4*)&Ps[(ty * 4 + i) * QSS + tx * 4] =
                make_float4(s[i][0], s[i][1], s[i][2], s[i][3]);
        }
        __syncthreads();

#pragma unroll 8
        for (int m = 0; m < 64; ++m) {
            float bb[4];
            *(float4*)bb = *(const float4*)&Vs[m * 64 + tx * 4];
#pragma unroll
            for (int i = 0; i < 4; ++i) {
                float av = Ps[(ty * 4 + i) * QSS + m];
#pragma unroll
                for (int j = 0; j < 4; ++j)
                    o[i][j] = fmaf(av, bb[j], o[i][j]);
            }
        }
    }

#pragma unroll
    for (int i = 0; i < 4; ++i) {
        float inv = 1.f / lrow[i];
        int r = r0 + ty * 4 + i;
        float4 v = make_float4(o[i][0] * inv, o[i][1] * inv,
                               o[i][2] * inv, o[i][3] * inv);
        *(float4*)(ao + (size_t)(b * N_ + r) * C_ + h * HD_ + tx * 4) = v;
    }
}

// ---------------------------------------------------------------------------
extern "C" void kernel_launch(void* const* d_in, const int* in_sizes, int n_in,
                              void* d_out, int out_size)
{
    const float* x      = (const float*)d_in[0];
    const float* w_qkv  = (const float*)d_in[1];
    const float* w_proj = (const float*)d_in[2];
    const float* b_proj = (const float*)d_in[3];
    float* out = (float*)d_out;

    float *qkv, *ao;
    cudaGetSymbolAddress((void**)&qkv, g_qkv);
    cudaGetSymbolAddress((void**)&ao,  g_ao);

    // 1) QKV projection: [8192,1024] @ [3072,1024]^T  (TF32 tensor cores)
    tf32_gemm_nt<false><<<dim3(QKV_COLS / 128, (B_ * N_) / 128), 256>>>(
        x, w_qkv, nullptr, qkv, B_ * N_, QKV_COLS, C_);

    // 2) Flash attention
    cudaFuncSetAttribute(attn_kernel,
                         cudaFuncAttributeMaxDynamicSharedMemorySize,
                         ATTN_SMEM_BYTES);
    attn_kernel<<<dim3(B_ * H_, N_ / 64), 256, ATTN_SMEM_BYTES>>>(qkv, ao);

    // 3) Output projection + bias: [8192,1024] @ [1024,1024]^T + b (TF32)
    tf32_gemm_nt<true><<<dim3(C_ / 128, (B_ * N_) / 128), 256>>>(
        ao, w_proj, b_proj, out, B_ * N_, C_, C_);
}

// round 11
// speedup vs baseline: 3.1206x; 1.8156x over previous
#include <cuda_runtime.h>
#include <cstdint>

#define B_  8
#define N_  1024
#define C_  1024
#define H_  16
#define HD_ 64
#define QKV_COLS (3 * C_)   // 3072

// Scratch (allocation-free: device globals)
__device__ float g_qkv[(size_t)B_ * N_ * QKV_COLS];  // [B*N, 3072]
__device__ float g_ao [(size_t)B_ * N_ * C_];        // [B*N, 1024] (b,n,h,hd)

__device__ __forceinline__ uint32_t f2tf32(float x) {
    uint32_t u;
    asm("cvt.rna.tf32.f32 %0, %1;" : "=r"(u) : "f"(x));
    return u;
}

__device__ __forceinline__ void mma_tf32(float* d, const uint32_t* a,
                                         const uint32_t* b) {
    asm volatile(
        "mma.sync.aligned.m16n8k8.row.col.f32.tf32.tf32.f32 "
        "{%0,%1,%2,%3}, {%4,%5,%6,%7}, {%8,%9}, {%0,%1,%2,%3};"
        : "+f"(d[0]), "+f"(d[1]), "+f"(d[2]), "+f"(d[3])
        : "r"(a[0]), "r"(a[1]), "r"(a[2]), "r"(a[3]),
          "r"(b[0]), "r"(b[1]));
}

// ---------------------------------------------------------------------------
// TF32 tensor-core NT GEMM: C[M,Nn] = A[M,K] @ B[Nn,K]^T (+ bias[Nn])
// ---------------------------------------------------------------------------
#define SSTR 36

template <bool BIAS>
__global__ __launch_bounds__(256, 2)
void tf32_gemm_nt(const float* __restrict__ A, const float* __restrict__ Bm,
                  const float* __restrict__ bias, float* __restrict__ Cc,
                  int M, int Nn, int K)
{
    __shared__ uint32_t As[128][SSTR];
    __shared__ uint32_t Bs[128][SSTR];

    const int tid  = threadIdx.x;
    const int lane = tid & 31;
    const int w    = tid >> 5;
    const int wm   = (w >> 2) * 64;
    const int wn   = (w & 3) * 32;
    const int g    = lane >> 2;
    const int c4   = lane & 3;
    const int m0   = blockIdx.y * 128;
    const int n0   = blockIdx.x * 128;

    const int lrow = tid >> 3;
    const int lcol = (tid & 7) * 4;

    float d[4][4][4];
#pragma unroll
    for (int i = 0; i < 4; ++i)
#pragma unroll
        for (int j = 0; j < 4; ++j)
#pragma unroll
            for (int r = 0; r < 4; ++r) d[i][j][r] = 0.f;

    for (int kt = 0; kt < K; kt += 32) {
#pragma unroll
        for (int it = 0; it < 4; ++it) {
            int row = lrow + it * 32;
            float4 va = *(const float4*)(A  + (size_t)(m0 + row) * K + kt + lcol);
            uint4 ta;
            ta.x = f2tf32(va.x); ta.y = f2tf32(va.y);
            ta.z = f2tf32(va.z); ta.w = f2tf32(va.w);
            *(uint4*)&As[row][lcol] = ta;
            float4 vb = *(const float4*)(Bm + (size_t)(n0 + row) * K + kt + lcol);
            uint4 tb;
            tb.x = f2tf32(vb.x); tb.y = f2tf32(vb.y);
            tb.z = f2tf32(vb.z); tb.w = f2tf32(vb.w);
            *(uint4*)&Bs[row][lcol] = tb;
        }
        __syncthreads();

#pragma unroll
        for (int kk = 0; kk < 32; kk += 8) {
            uint32_t af[4][4], bf[4][2];
#pragma unroll
            for (int i = 0; i < 4; ++i) {
                int mr = wm + i * 16 + g;
                af[i][0] = As[mr    ][kk + c4];
                af[i][1] = As[mr + 8][kk + c4];
                af[i][2] = As[mr    ][kk + c4 + 4];
                af[i][3] = As[mr + 8][kk + c4 + 4];
            }
#pragma unroll
            for (int j = 0; j < 4; ++j) {
                int nr = wn + j * 8 + g;
                bf[j][0] = Bs[nr][kk + c4];
                bf[j][1] = Bs[nr][kk + c4 + 4];
            }
#pragma unroll
            for (int i = 0; i < 4; ++i)
#pragma unroll
                for (int j = 0; j < 4; ++j)
                    mma_tf32(d[i][j], af[i], bf[j]);
        }
        __syncthreads();
    }

#pragma unroll
    for (int i = 0; i < 4; ++i) {
        int row = m0 + wm + i * 16 + g;
#pragma unroll
        for (int j = 0; j < 4; ++j) {
            int col = n0 + wn + j * 8 + c4 * 2;
            float b0 = 0.f, b1 = 0.f;
            if (BIAS) { b0 = bias[col]; b1 = bias[col + 1]; }
            *(float2*)(Cc + (size_t)row * Nn + col) =
                make_float2(d[i][j][0] + b0, d[i][j][1] + b1);
            *(float2*)(Cc + (size_t)(row + 8) * Nn + col) =
                make_float2(d[i][j][2] + b0, d[i][j][3] + b1);
        }
    }
}

// ---------------------------------------------------------------------------
// TF32 tensor-core flash attention.
// CTA = (b,h) x 128-query tile, 8 warps x 16 rows, 16 key-tiles of 64.
// smem (tf32 words, stride 68 -> fragment bank pattern (4g+c4)&31):
//   Qs[128][68] (pre-scaled), Ps[128][68], Ks[64][68] ([key][d]),
//   Vt[64][68]  ([d][key]).
// ---------------------------------------------------------------------------
#define ASTR 68
#define ATTN_SMEM_WORDS (128 * ASTR * 2 + 64 * ASTR * 2)
#define ATTN_SMEM_BYTES (ATTN_SMEM_WORDS * 4)

__global__ __launch_bounds__(256)
void attn_kernel(const float* __restrict__ qkv, float* __restrict__ ao)
{
    extern __shared__ uint32_t smu[];
    uint32_t* Qs = smu;                        // [128][68]
    uint32_t* Ps = smu + 128 * ASTR;           // [128][68]
    uint32_t* Ks = smu + 256 * ASTR;           // [64][68]
    uint32_t* Vt = smu + 320 * ASTR;           // [64][68]

    const int tid  = threadIdx.x;
    const int lane = tid & 31;
    const int w    = tid >> 5;            // 0..7
    const int wm   = w * 16;              // warp's query-row offset
    const int g    = lane >> 2;           // 0..7
    const int c4   = lane & 3;            // 0..3
    const int bh   = blockIdx.x;
    const int b    = bh >> 4;
    const int h    = bh & 15;
    const int r0   = blockIdx.y * 128;
    const float scale = 0.125f;

    // ---- load Q tile (pre-scaled, tf32) ----
    const float* qb = qkv + (size_t)b * N_ * QKV_COLS + h * HD_;
#pragma unroll
    for (int it = 0; it < 8; ++it) {
        int e  = tid + it * 256;          // 0..2047
        int r  = e >> 4;                  // 0..127
        int dd = (e & 15) << 2;           // 0..60
        float4 v = *(const float4*)(qb + (size_t)(r0 + r) * QKV_COLS + dd);
        uint4 t;
        t.x = f2tf32(v.x * scale); t.y = f2tf32(v.y * scale);
        t.z = f2tf32(v.z * scale); t.w = f2tf32(v.w * scale);
        *(uint4*)&Qs[r * ASTR + dd] = t;
    }

    float o[8][4];
    float m0r = -1e30f, m1r = -1e30f, l0 = 0.f, l1 = 0.f;
#pragma unroll
    for (int j = 0; j < 8; ++j)
#pragma unroll
        for (int r = 0; r < 4; ++r) o[j][r] = 0.f;

    for (int t = 0; t < 16; ++t) {
        __syncthreads();   // prior tile's K/V reads done (also makes Q visible)

        // ---- load K [key][d] (row loads) ----
#pragma unroll
        for (int it = 0; it < 4; ++it) {
            int e  = tid + it * 256;          // 0..1023
            int m  = e >> 4;                  // 0..63
            int dd = (e & 15) << 2;
            const float* kb = qkv + (size_t)(b * N_ + t * 64 + m) * QKV_COLS
                              + C_ + h * HD_ + dd;
            float4 v = *(const float4*)kb;
            uint4 tk;
            tk.x = f2tf32(v.x); tk.y = f2tf32(v.y);
            tk.z = f2tf32(v.z); tk.w = f2tf32(v.w);
            *(uint4*)&Ks[m * ASTR + dd] = tk;
        }
        // ---- load V transposed -> Vt[d][key] (column loads, STS.128) ----
#pragma unroll
        for (int it = 0; it < 4; ++it) {
            int e  = tid + it * 256;          // 0..1023
            int dd = e & 63;
            int m4 = (e >> 6) << 2;           // 0..60
            const float* vb = qkv + (size_t)(b * N_ + t * 64 + m4) * QKV_COLS
                              + 2 * C_ + h * HD_ + dd;
            uint4 tv;
            tv.x = f2tf32(vb[0]);
            tv.y = f2tf32(vb[QKV_COLS]);
            tv.z = f2tf32(vb[2 * QKV_COLS]);
            tv.w = f2tf32(vb[3 * QKV_COLS]);
            *(uint4*)&Vt[dd * ASTR + m4] = tv;
        }
        __syncthreads();

        // ---- S = (Q*scale) @ K^T : 8 n-tiles x 8 k-steps of mma ----
        float s[8][4];
#pragma unroll
        for (int j = 0; j < 8; ++j)
#pragma unroll
            for (int r = 0; r < 4; ++r) s[j][r] = 0.f;

#pragma unroll
        for (int kk = 0; kk < 64; kk += 8) {
            uint32_t a[4];
            a[0] = Qs[(wm + g)     * ASTR + kk + c4];
            a[1] = Qs[(wm + g + 8) * ASTR + kk + c4];
            a[2] = Qs[(wm + g)     * ASTR + kk + c4 + 4];
            a[3] = Qs[(wm + g + 8) * ASTR + kk + c4 + 4];
#pragma unroll
            for (int j = 0; j < 8; ++j) {
                uint32_t bb[2];
                bb[0] = Ks[(j * 8 + g) * ASTR + kk + c4];
                bb[1] = Ks[(j * 8 + g) * ASTR + kk + c4 + 4];
                mma_tf32(s[j], a, bb);
            }
        }

        // ---- online softmax on fragments ----
        // row g holds s[j][0..1]; row g+8 holds s[j][2..3]; stats over 4 lanes
        float rm0 = -1e30f, rm1 = -1e30f;
#pragma unroll
        for (int j = 0; j < 8; ++j) {
            rm0 = fmaxf(rm0, fmaxf(s[j][0], s[j][1]));
            rm1 = fmaxf(rm1, fmaxf(s[j][2], s[j][3]));
        }
#pragma unroll
        for (int off = 1; off <= 2; off <<= 1) {
            rm0 = fmaxf(rm0, __shfl_xor_sync(0xffffffffu, rm0, off));
            rm1 = fmaxf(rm1, __shfl_xor_sync(0xffffffffu, rm1, off));
        }
        float mn0 = fmaxf(m0r, rm0), mn1 = fmaxf(m1r, rm1);
        float al0 = __expf(m0r - mn0), al1 = __expf(m1r - mn1);
        float rs0 = 0.f, rs1 = 0.f;
#pragma unroll
        for (int j = 0; j < 8; ++j) {
            s[j][0] = __expf(s[j][0] - mn0);
            s[j][1] = __expf(s[j][1] - mn0);
            s[j][2] = __expf(s[j][2] - mn1);
            s[j][3] = __expf(s[j][3] - mn1);
            rs0 += s[j][0] + s[j][1];
            rs1 += s[j][2] + s[j][3];
        }
#pragma unroll
        for (int off = 1; off <= 2; off <<= 1) {
            rs0 += __shfl_xor_sync(0xffffffffu, rs0, off);
            rs1 += __shfl_xor_sync(0xffffffffu, rs1, off);
        }
        l0 = l0 * al0 + rs0;  m0r = mn0;
        l1 = l1 * al1 + rs1;  m1r = mn1;
#pragma unroll
        for (int j = 0; j < 8; ++j) {
            o[j][0] *= al0; o[j][1] *= al0;
            o[j][2] *= al1; o[j][3] *= al1;
            // store P (tf32) for the A-fragment reshape
            uint2 p0 = make_uint2(f2tf32(s[j][0]), f2tf32(s[j][1]));
            uint2 p1 = make_uint2(f2tf32(s[j][2]), f2tf32(s[j][3]));
            *(uint2*)&Ps[(wm + g)     * ASTR + j * 8 + c4 * 2] = p0;
            *(uint2*)&Ps[(wm + g + 8) * ASTR + j * 8 + c4 * 2] = p1;
        }
        __syncwarp();   // P region is warp-private: warp-level ordering suffices

        // ---- O += P @ V : A from Ps, B from Vt[d][key] ----
#pragma unroll
        for (int kk = 0; kk < 64; kk += 8) {
            uint32_t a[4];
            a[0] = Ps[(wm + g)     * ASTR + kk + c4];
            a[1] = Ps[(wm + g + 8) * ASTR + kk + c4];
            a[2] = Ps[(wm + g)     * ASTR + kk + c4 + 4];
            a[3] = Ps[(wm + g + 8) * ASTR + kk + c4 + 4];
#pragma unroll
            for (int j = 0; j < 8; ++j) {
                uint32_t bb[2];
                bb[0] = Vt[(j * 8 + g) * ASTR + kk + c4];
                bb[1] = Vt[(j * 8 + g) * ASTR + kk + c4 + 4];
                mma_tf32(o[j], a, bb);
            }
        }
    }

    // ---- epilogue: O / l -> ao[b,n,h,hd] ----
    float inv0 = 1.f / l0, inv1 = 1.f / l1;
    int row0 = r0 + wm + g;
    float* aob = ao + (size_t)(b * N_) * C_ + h * HD_;
#pragma unroll
    for (int j = 0; j < 8; ++j) {
        int col = j * 8 + c4 * 2;
        *(float2*)(aob + (size_t)row0 * C_ + col) =
            make_float2(o[j][0] * inv0, o[j][1] * inv0);
        *(float2*)(aob + (size_t)(row0 + 8) * C_ + col) =
            make_float2(o[j][2] * inv1, o[j][3] * inv1);
    }
}

// ---------------------------------------------------------------------------
extern "C" void kernel_launch(void* const* d_in, const int* in_sizes, int n_in,
                              void* d_out, int out_size)
{
    const float* x      = (const float*)d_in[0];
    const float* w_qkv  = (const float*)d_in[1];
    const float* w_proj = (const float*)d_in[2];
    const float* b_proj = (const float*)d_in[3];
    float* out = (float*)d_out;

    float *qkv, *ao;
    cudaGetSymbolAddress((void**)&qkv, g_qkv);
    cudaGetSymbolAddress((void**)&ao,  g_ao);

    // 1) QKV projection (TF32 tensor cores)
    tf32_gemm_nt<false><<<dim3(QKV_COLS / 128, (B_ * N_) / 128), 256>>>(
        x, w_qkv, nullptr, qkv, B_ * N_, QKV_COLS, C_);

    // 2) TF32 tensor-core flash attention
    cudaFuncSetAttribute(attn_kernel,
                         cudaFuncAttributeMaxDynamicSharedMemorySize,
                         ATTN_SMEM_BYTES);
    attn_kernel<<<dim3(B_ * H_, N_ / 128), 256, ATTN_SMEM_BYTES>>>(qkv, ao);

    // 3) Output projection + bias (TF32 tensor cores)
    tf32_gemm_nt<true><<<dim3(C_ / 128, (B_ * N_) / 128), 256>>>(
        ao, w_proj, b_proj, out, B_ * N_, C_, C_);
}

// round 12
// speedup vs baseline: 3.3775x; 1.0823x over previous
#include <cuda_runtime.h>
#include <cstdint>

#define B_  8
#define N_  1024
#define C_  1024
#define H_  16
#define HD_ 64
#define QKV_COLS (3 * C_)   // 3072

// Scratch (allocation-free: device globals)
__device__ float    g_qkv[(size_t)B_ * N_ * QKV_COLS]; // [B*N, 3072] fp32
__device__ float    g_ao [(size_t)B_ * N_ * C_];       // [B*N, 1024] tf32-rounded
__device__ uint32_t g_xr [(size_t)B_ * N_ * C_];       // x  rounded to tf32
__device__ uint32_t g_wqr[(size_t)QKV_COLS * C_];      // w_qkv rounded
__device__ uint32_t g_wpr[(size_t)C_ * C_];            // w_proj rounded

__device__ __forceinline__ uint32_t f2tf32(float x) {
    uint32_t u;
    asm("cvt.rna.tf32.f32 %0, %1;" : "=r"(u) : "f"(x));
    return u;
}

__device__ __forceinline__ void mma_tf32(float* d, const uint32_t* a,
                                         const uint32_t* b) {
    asm volatile(
        "mma.sync.aligned.m16n8k8.row.col.f32.tf32.tf32.f32 "
        "{%0,%1,%2,%3}, {%4,%5,%6,%7}, {%8,%9}, {%0,%1,%2,%3};"
        : "+f"(d[0]), "+f"(d[1]), "+f"(d[2]), "+f"(d[3])
        : "r"(a[0]), "r"(a[1]), "r"(a[2]), "r"(a[3]),
          "r"(b[0]), "r"(b[1]));
}

__device__ __forceinline__ void cp16(void* s, const void* g) {
    uint32_t sa = (uint32_t)__cvta_generic_to_shared(s);
    asm volatile("cp.async.cg.shared.global [%0], [%1], 16;" :: "r"(sa), "l"(g));
}
__device__ __forceinline__ void cp_commit() {
    asm volatile("cp.async.commit_group;");
}
__device__ __forceinline__ void cp_wait1() {
    asm volatile("cp.async.wait_group 1;");
}
__device__ __forceinline__ void cp_wait0() {
    asm volatile("cp.async.wait_group 0;");
}

// ---------------------------------------------------------------------------
// Prepass: round fp32 -> tf32 bits (RNA), vectorized.
// ---------------------------------------------------------------------------
__global__ __launch_bounds__(256)
void round_tf32_kernel(const float* __restrict__ in, uint32_t* __restrict__ outp)
{
    size_t i = ((size_t)blockIdx.x * 256 + threadIdx.x) * 4;
    float4 v = *(const float4*)(in + i);
    uint4 t;
    t.x = f2tf32(v.x); t.y = f2tf32(v.y);
    t.z = f2tf32(v.z); t.w = f2tf32(v.w);
    *(uint4*)(outp + i) = t;
}

// ---------------------------------------------------------------------------
// Double-buffered cp.async TF32 NT GEMM: C[M,Nn] = A[M,K] @ B[Nn,K]^T (+bias)
// A, B already tf32-rounded in memory. 128x128x32 tiles, 256 thr, 8 warps.
// ---------------------------------------------------------------------------
#define SSTR 36
#define GEMM_SMEM_BYTES (2 * 2 * 128 * SSTR * 4)   // 73728

template <bool BIAS>
__global__ __launch_bounds__(256, 2)
void tf32_gemm_db(const uint32_t* __restrict__ A, const uint32_t* __restrict__ Bm,
                  const float* __restrict__ bias, float* __restrict__ Cc,
                  int M, int Nn, int K)
{
    extern __shared__ uint32_t sh[];
    // layout: As[2][128][SSTR] then Bs[2][128][SSTR]
    uint32_t* As = sh;
    uint32_t* Bs = sh + 2 * 128 * SSTR;

    const int tid  = threadIdx.x;
    const int lane = tid & 31;
    const int w    = tid >> 5;
    const int wm   = (w >> 2) * 64;
    const int wn   = (w & 3) * 32;
    const int g    = lane >> 2;
    const int c4   = lane & 3;
    const int m0   = blockIdx.y * 128;
    const int n0   = blockIdx.x * 128;

    const int lrow = tid >> 3;            // 0..31 (+32/iter)
    const int lcol = (tid & 7) * 4;       // 0..28

    float d[4][4][4];
#pragma unroll
    for (int i = 0; i < 4; ++i)
#pragma unroll
        for (int j = 0; j < 4; ++j)
#pragma unroll
            for (int r = 0; r < 4; ++r) d[i][j][r] = 0.f;

    auto issue = [&](int kt, int buf) {
        uint32_t* Ab = As + buf * 128 * SSTR;
        uint32_t* Bb = Bs + buf * 128 * SSTR;
#pragma unroll
        for (int it = 0; it < 4; ++it) {
            int row = lrow + it * 32;
            cp16(&Ab[row * SSTR + lcol], A  + (size_t)(m0 + row) * K + kt + lcol);
            cp16(&Bb[row * SSTR + lcol], Bm + (size_t)(n0 + row) * K + kt + lcol);
        }
        cp_commit();
    };

    const int nk = K / 32;
    issue(0, 0);

    for (int t = 0; t < nk; ++t) {
        if (t + 1 < nk) { issue((t + 1) * 32, (t + 1) & 1); cp_wait1(); }
        else            { cp_wait0(); }
        __syncthreads();

        const uint32_t* Ab = As + (t & 1) * 128 * SSTR;
        const uint32_t* Bb = Bs + (t & 1) * 128 * SSTR;
#pragma unroll
        for (int kk = 0; kk < 32; kk += 8) {
            uint32_t af[4][4], bf[4][2];
#pragma unroll
            for (int i = 0; i < 4; ++i) {
                int mr = wm + i * 16 + g;
                af[i][0] = Ab[mr * SSTR + kk + c4];
                af[i][1] = Ab[(mr + 8) * SSTR + kk + c4];
                af[i][2] = Ab[mr * SSTR + kk + c4 + 4];
                af[i][3] = Ab[(mr + 8) * SSTR + kk + c4 + 4];
            }
#pragma unroll
            for (int j = 0; j < 4; ++j) {
                int nr = wn + j * 8 + g;
                bf[j][0] = Bb[nr * SSTR + kk + c4];
                bf[j][1] = Bb[nr * SSTR + kk + c4 + 4];
            }
#pragma unroll
            for (int i = 0; i < 4; ++i)
#pragma unroll
                for (int j = 0; j < 4; ++j)
                    mma_tf32(d[i][j], af[i], bf[j]);
        }
        __syncthreads();
    }

#pragma unroll
    for (int i = 0; i < 4; ++i) {
        int row = m0 + wm + i * 16 + g;
#pragma unroll
        for (int j = 0; j < 4; ++j) {
            int col = n0 + wn + j * 8 + c4 * 2;
            float b0 = 0.f, b1 = 0.f;
            if (BIAS) { b0 = bias[col]; b1 = bias[col + 1]; }
            *(float2*)(Cc + (size_t)row * Nn + col) =
                make_float2(d[i][j][0] + b0, d[i][j][1] + b1);
            *(float2*)(Cc + (size_t)(row + 8) * Nn + col) =
                make_float2(d[i][j][2] + b0, d[i][j][3] + b1);
        }
    }
}

// ---------------------------------------------------------------------------
// TF32 tensor-core flash attention with K/V register prefetch.
// CTA = (b,h) x 128-query tile, 8 warps x 16 rows, 16 key-tiles of 64.
// ---------------------------------------------------------------------------
#define ASTR 68
#define ATTN_SMEM_WORDS (128 * ASTR * 2 + 64 * ASTR * 2)
#define ATTN_SMEM_BYTES (ATTN_SMEM_WORDS * 4)

__global__ __launch_bounds__(256)
void attn_kernel(const float* __restrict__ qkv, float* __restrict__ ao)
{
    extern __shared__ uint32_t smu[];
    uint32_t* Qs = smu;                        // [128][68]
    uint32_t* Ps = smu + 128 * ASTR;           // [128][68]
    uint32_t* Ks = smu + 256 * ASTR;           // [64][68]
    uint32_t* Vt = smu + 320 * ASTR;           // [64][68]

    const int tid  = threadIdx.x;
    const int lane = tid & 31;
    const int w    = tid >> 5;
    const int wm   = w * 16;
    const int g    = lane >> 2;
    const int c4   = lane & 3;
    const int bh   = blockIdx.x;
    const int b    = bh >> 4;
    const int h    = bh & 15;
    const int r0   = blockIdx.y * 128;
    const float scale = 0.125f;

    // ---- load Q tile (pre-scaled, tf32) ----
    const float* qb = qkv + (size_t)b * N_ * QKV_COLS + h * HD_;
#pragma unroll
    for (int it = 0; it < 8; ++it) {
        int e  = tid + it * 256;
        int r  = e >> 4;
        int dd = (e & 15) << 2;
        float4 v = *(const float4*)(qb + (size_t)(r0 + r) * QKV_COLS + dd);
        uint4 t;
        t.x = f2tf32(v.x * scale); t.y = f2tf32(v.y * scale);
        t.z = f2tf32(v.z * scale); t.w = f2tf32(v.w * scale);
        *(uint4*)&Qs[r * ASTR + dd] = t;
    }

    // K/V prefetch registers
    float4 kreg[4];
    float  vreg[4][4];
    auto prefetch = [&](int t) {
#pragma unroll
        for (int it = 0; it < 4; ++it) {
            int e  = tid + it * 256;
            int m  = e >> 4;
            int dd = (e & 15) << 2;
            kreg[it] = *(const float4*)(qkv
                + (size_t)(b * N_ + t * 64 + m) * QKV_COLS + C_ + h * HD_ + dd);
        }
#pragma unroll
        for (int it = 0; it < 4; ++it) {
            int e  = tid + it * 256;
            int dd = e & 63;
            int m4 = (e >> 6) << 2;
            const float* vb = qkv
                + (size_t)(b * N_ + t * 64 + m4) * QKV_COLS + 2 * C_ + h * HD_ + dd;
            vreg[it][0] = vb[0];
            vreg[it][1] = vb[QKV_COLS];
            vreg[it][2] = vb[2 * QKV_COLS];
            vreg[it][3] = vb[3 * QKV_COLS];
        }
    };
    prefetch(0);

    float o[8][4];
    float m0r = -1e30f, m1r = -1e30f, l0 = 0.f, l1 = 0.f;
#pragma unroll
    for (int j = 0; j < 8; ++j)
#pragma unroll
        for (int r = 0; r < 4; ++r) o[j][r] = 0.f;

    for (int t = 0; t < 16; ++t) {
        __syncthreads();   // prior tile's K/V reads done

        // ---- store prefetched K [key][d] and V^T [d][key] ----
#pragma unroll
        for (int it = 0; it < 4; ++it) {
            int e  = tid + it * 256;
            int m  = e >> 4;
            int dd = (e & 15) << 2;
            uint4 tk;
            tk.x = f2tf32(kreg[it].x); tk.y = f2tf32(kreg[it].y);
            tk.z = f2tf32(kreg[it].z); tk.w = f2tf32(kreg[it].w);
            *(uint4*)&Ks[m * ASTR + dd] = tk;
        }
#pragma unroll
        for (int it = 0; it < 4; ++it) {
            int e  = tid + it * 256;
            int dd = e & 63;
            int m4 = (e >> 6) << 2;
            uint4 tv;
            tv.x = f2tf32(vreg[it][0]); tv.y = f2tf32(vreg[it][1]);
            tv.z = f2tf32(vreg[it][2]); tv.w = f2tf32(vreg[it][3]);
            *(uint4*)&Vt[dd * ASTR + m4] = tv;
        }
        __syncthreads();

        if (t + 1 < 16) prefetch(t + 1);   // overlaps with compute below

        // ---- S = (Q*scale) @ K^T ----
        float s[8][4];
#pragma unroll
        for (int j = 0; j < 8; ++j)
#pragma unroll
            for (int r = 0; r < 4; ++r) s[j][r] = 0.f;

#pragma unroll
        for (int kk = 0; kk < 64; kk += 8) {
            uint32_t a[4];
            a[0] = Qs[(wm + g)     * ASTR + kk + c4];
            a[1] = Qs[(wm + g + 8) * ASTR + kk + c4];
            a[2] = Qs[(wm + g)     * ASTR + kk + c4 + 4];
            a[3] = Qs[(wm + g + 8) * ASTR + kk + c4 + 4];
#pragma unroll
            for (int j = 0; j < 8; ++j) {
                uint32_t bb[2];
                bb[0] = Ks[(j * 8 + g) * ASTR + kk + c4];
                bb[1] = Ks[(j * 8 + g) * ASTR + kk + c4 + 4];
                mma_tf32(s[j], a, bb);
            }
        }

        // ---- online softmax on fragments ----
        float rm0 = -1e30f, rm1 = -1e30f;
#pragma unroll
        for (int j = 0; j < 8; ++j) {
            rm0 = fmaxf(rm0, fmaxf(s[j][0], s[j][1]));
            rm1 = fmaxf(rm1, fmaxf(s[j][2], s[j][3]));
        }
#pragma unroll
        for (int off = 1; off <= 2; off <<= 1) {
            rm0 = fmaxf(rm0, __shfl_xor_sync(0xffffffffu, rm0, off));
            rm1 = fmaxf(rm1, __shfl_xor_sync(0xffffffffu, rm1, off));
        }
        float mn0 = fmaxf(m0r, rm0), mn1 = fmaxf(m1r, rm1);
        float al0 = __expf(m0r - mn0), al1 = __expf(m1r - mn1);
        float rs0 = 0.f, rs1 = 0.f;
#pragma unroll
        for (int j = 0; j < 8; ++j) {
            s[j][0] = __expf(s[j][0] - mn0);
            s[j][1] = __expf(s[j][1] - mn0);
            s[j][2] = __expf(s[j][2] - mn1);
            s[j][3] = __expf(s[j][3] - mn1);
            rs0 += s[j][0] + s[j][1];
            rs1 += s[j][2] + s[j][3];
        }
#pragma unroll
        for (int off = 1; off <= 2; off <<= 1) {
            rs0 += __shfl_xor_sync(0xffffffffu, rs0, off);
            rs1 += __shfl_xor_sync(0xffffffffu, rs1, off);
        }
        l0 = l0 * al0 + rs0;  m0r = mn0;
        l1 = l1 * al1 + rs1;  m1r = mn1;
#pragma unroll
        for (int j = 0; j < 8; ++j) {
            o[j][0] *= al0; o[j][1] *= al0;
            o[j][2] *= al1; o[j][3] *= al1;
            uint2 p0 = make_uint2(f2tf32(s[j][0]), f2tf32(s[j][1]));
            uint2 p1 = make_uint2(f2tf32(s[j][2]), f2tf32(s[j][3]));
            *(uint2*)&Ps[(wm + g)     * ASTR + j * 8 + c4 * 2] = p0;
            *(uint2*)&Ps[(wm + g + 8) * ASTR + j * 8 + c4 * 2] = p1;
        }
        __syncwarp();   // P region is warp-private

        // ---- O += P @ V ----
#pragma unroll
        for (int kk = 0; kk < 64; kk += 8) {
            uint32_t a[4];
            a[0] = Ps[(wm + g)     * ASTR + kk + c4];
            a[1] = Ps[(wm + g + 8) * ASTR + kk + c4];
            a[2] = Ps[(wm + g)     * ASTR + kk + c4 + 4];
            a[3] = Ps[(wm + g + 8) * ASTR + kk + c4 + 4];
#pragma unroll
            for (int j = 0; j < 8; ++j) {
                uint32_t bb[2];
                bb[0] = Vt[(j * 8 + g) * ASTR + kk + c4];
                bb[1] = Vt[(j * 8 + g) * ASTR + kk + c4 + 4];
                mma_tf32(o[j], a, bb);
            }
        }
    }

    // ---- epilogue: (O / l), tf32-rounded, -> ao[b,n,h,hd] ----
    float inv0 = 1.f / l0, inv1 = 1.f / l1;
    int row0 = r0 + wm + g;
    float* aob = ao + (size_t)(b * N_) * C_ + h * HD_;
#pragma unroll
    for (int j = 0; j < 8; ++j) {
        int col = j * 8 + c4 * 2;
        float2 v0 = make_float2(__uint_as_float(f2tf32(o[j][0] * inv0)),
                                __uint_as_float(f2tf32(o[j][1] * inv0)));
        float2 v1 = make_float2(__uint_as_float(f2tf32(o[j][2] * inv1)),
                                __uint_as_float(f2tf32(o[j][3] * inv1)));
        *(float2*)(aob + (size_t)row0 * C_ + col) = v0;
        *(float2*)(aob + (size_t)(row0 + 8) * C_ + col) = v1;
    }
}

// ---------------------------------------------------------------------------
extern "C" void kernel_launch(void* const* d_in, const int* in_sizes, int n_in,
                              void* d_out, int out_size)
{
    const float* x      = (const float*)d_in[0];
    const float* w_qkv  = (const float*)d_in[1];
    const float* w_proj = (const float*)d_in[2];
    const float* b_proj = (const float*)d_in[3];
    float* out = (float*)d_out;

    float *qkv, *ao;
    uint32_t *xr, *wqr, *wpr;
    cudaGetSymbolAddress((void**)&qkv, g_qkv);
    cudaGetSymbolAddress((void**)&ao,  g_ao);
    cudaGetSymbolAddress((void**)&xr,  g_xr);
    cudaGetSymbolAddress((void**)&wqr, g_wqr);
    cudaGetSymbolAddress((void**)&wpr, g_wpr);

    // 0) Pre-round inputs to tf32 (RNA) once.
    round_tf32_kernel<<<(B_ * N_ * C_) / 1024, 256>>>(x, xr);
    round_tf32_kernel<<<(QKV_COLS * C_) / 1024, 256>>>(w_qkv, wqr);
    round_tf32_kernel<<<(C_ * C_) / 1024, 256>>>(w_proj, wpr);

    cudaFuncSetAttribute(tf32_gemm_db<false>,
                         cudaFuncAttributeMaxDynamicSharedMemorySize,
                         GEMM_SMEM_BYTES);
    cudaFuncSetAttribute(tf32_gemm_db<true>,
                         cudaFuncAttributeMaxDynamicSharedMemorySize,
                         GEMM_SMEM_BYTES);
    cudaFuncSetAttribute(attn_kernel,
                         cudaFuncAttributeMaxDynamicSharedMemorySize,
                         ATTN_SMEM_BYTES);

    // 1) QKV projection (double-buffered cp.async TF32)
    tf32_gemm_db<false><<<dim3(QKV_COLS / 128, (B_ * N_) / 128), 256,
                          GEMM_SMEM_BYTES>>>(
        xr, wqr, nullptr, qkv, B_ * N_, QKV_COLS, C_);

    // 2) TF32 flash attention (writes tf32-rounded ao)
    attn_kernel<<<dim3(B_ * H_, N_ / 128), 256, ATTN_SMEM_BYTES>>>(qkv, ao);

    // 3) Output projection + bias
    tf32_gemm_db<true><<<dim3(C_ / 128, (B_ * N_) / 128), 256,
                         GEMM_SMEM_BYTES>>>(
        (const uint32_t*)ao, wpr, b_proj, out, B_ * N_, C_, C_);
}

// round 13
// speedup vs baseline: 3.5883x; 1.0624x over previous
#include <cuda_runtime.h>
#include <cstdint>

#define B_  8
#define N_  1024
#define C_  1024
#define H_  16
#define HD_ 64
#define QKV_COLS (3 * C_)   // 3072

// Scratch (allocation-free: device globals)
__device__ float    g_qkv[(size_t)B_ * N_ * QKV_COLS]; // [B*N, 3072] fp32
__device__ float    g_ao [(size_t)B_ * N_ * C_];       // [B*N, 1024] tf32-rounded
__device__ uint32_t g_xr [(size_t)B_ * N_ * C_];       // x  rounded to tf32
__device__ uint32_t g_wqr[(size_t)QKV_COLS * C_];      // w_qkv rounded
__device__ uint32_t g_wpr[(size_t)C_ * C_];            // w_proj rounded

__device__ __forceinline__ uint32_t f2tf32(float x) {
    uint32_t u;
    asm("cvt.rna.tf32.f32 %0, %1;" : "=r"(u) : "f"(x));
    return u;
}

__device__ __forceinline__ void mma_tf32(float* d, const uint32_t* a,
                                         const uint32_t* b) {
    asm volatile(
        "mma.sync.aligned.m16n8k8.row.col.f32.tf32.tf32.f32 "
        "{%0,%1,%2,%3}, {%4,%5,%6,%7}, {%8,%9}, {%0,%1,%2,%3};"
        : "+f"(d[0]), "+f"(d[1]), "+f"(d[2]), "+f"(d[3])
        : "r"(a[0]), "r"(a[1]), "r"(a[2]), "r"(a[3]),
          "r"(b[0]), "r"(b[1]));
}

// ldmatrix.x4 over 32-bit k-major rows: for tf32 mma fragments the b16 lane
// mapping (lane L -> row L/4, 16B row chunk -> tf32 col L%4) matches exactly.
__device__ __forceinline__ void ldsm_x4(uint32_t* r, const void* p) {
    uint32_t a = (uint32_t)__cvta_generic_to_shared(p);
    asm volatile("ldmatrix.sync.aligned.m8n8.x4.shared.b16 {%0,%1,%2,%3}, [%4];"
        : "=r"(r[0]), "=r"(r[1]), "=r"(r[2]), "=r"(r[3]) : "r"(a));
}

__device__ __forceinline__ void cp16(void* s, const void* g) {
    uint32_t sa = (uint32_t)__cvta_generic_to_shared(s);
    asm volatile("cp.async.cg.shared.global [%0], [%1], 16;" :: "r"(sa), "l"(g));
}
__device__ __forceinline__ void cp_commit() {
    asm volatile("cp.async.commit_group;");
}
__device__ __forceinline__ void cp_wait1() {
    asm volatile("cp.async.wait_group 1;");
}
__device__ __forceinline__ void cp_wait0() {
    asm volatile("cp.async.wait_group 0;");
}

// ---------------------------------------------------------------------------
// Prepass: round fp32 -> tf32 bits (RNA), vectorized.
// ---------------------------------------------------------------------------
__global__ __launch_bounds__(256)
void round_tf32_kernel(const float* __restrict__ in, uint32_t* __restrict__ outp)
{
    size_t i = ((size_t)blockIdx.x * 256 + threadIdx.x) * 4;
    float4 v = *(const float4*)(in + i);
    uint4 t;
    t.x = f2tf32(v.x); t.y = f2tf32(v.y);
    t.z = f2tf32(v.z); t.w = f2tf32(v.w);
    *(uint4*)(outp + i) = t;
}

// ---------------------------------------------------------------------------
// 3-stage cp.async TF32 NT GEMM: C[M,Nn] = A[M,K] @ B[Nn,K]^T (+bias)
// 128x128x32 tiles, 256 thr, 8 warps (2x4 -> 64x32 warp tile), ldmatrix frags.
// ---------------------------------------------------------------------------
#define SSTR 36
#define STAGE_WORDS (256 * SSTR)                 // A(128) + B(128) rows
#define GEMM_SMEM_BYTES (3 * STAGE_WORDS * 4)    // 110592

template <bool BIAS>
__global__ __launch_bounds__(256, 2)
void tf32_gemm_db(const uint32_t* __restrict__ A, const uint32_t* __restrict__ Bm,
                  const float* __restrict__ bias, float* __restrict__ Cc,
                  int M, int Nn, int K)
{
    extern __shared__ uint32_t sh[];

    const int tid  = threadIdx.x;
    const int lane = tid & 31;
    const int w    = tid >> 5;
    const int wm   = (w >> 2) * 64;
    const int wn   = (w & 3) * 32;
    const int g    = lane >> 2;
    const int c4   = lane & 3;
    const int m0   = blockIdx.y * 128;
    const int n0   = blockIdx.x * 128;

    // ldmatrix per-lane row/col selectors
    const int arow = (lane & 7) + (((lane >> 3) & 1) << 3);  // A/Q/P rows
    const int acol = ((lane >> 4) & 1) << 2;                 // k lo/hi
    const int brow = ((lane >> 4) << 3) + (lane & 7);        // B rows (j pair)
    const int bcol = ((lane >> 3) & 1) << 2;

    const int lrow = tid >> 3;            // 0..31 (+32/iter)
    const int lcol = (tid & 7) * 4;       // 0..28

    float d[4][4][4];
#pragma unroll
    for (int i = 0; i < 4; ++i)
#pragma unroll
        for (int j = 0; j < 4; ++j)
#pragma unroll
            for (int r = 0; r < 4; ++r) d[i][j][r] = 0.f;

    auto issue = [&](int kt, int buf) {
        uint32_t* Ab = sh + buf * STAGE_WORDS;
        uint32_t* Bb = Ab + 128 * SSTR;
#pragma unroll
        for (int it = 0; it < 4; ++it) {
            int row = lrow + it * 32;
            cp16(&Ab[row * SSTR + lcol], A  + (size_t)(m0 + row) * K + kt + lcol);
            cp16(&Bb[row * SSTR + lcol], Bm + (size_t)(n0 + row) * K + kt + lcol);
        }
        cp_commit();
    };

    const int nk = K / 32;
    issue(0, 0);
    issue(32, 1);

    int buf = 0;
    for (int t = 0; t < nk; ++t) {
        if (t + 2 < nk) cp_wait1(); else cp_wait0();
        __syncthreads();
        if (t + 2 < nk) issue((t + 2) * 32, (t + 2) % 3);

        const uint32_t* Ab = sh + buf * STAGE_WORDS;
        const uint32_t* Bb = Ab + 128 * SSTR;
#pragma unroll
        for (int kk = 0; kk < 32; kk += 8) {
            uint32_t af[4][4], bf[2][4];
#pragma unroll
            for (int i = 0; i < 4; ++i)
                ldsm_x4(af[i], &Ab[(wm + i * 16 + arow) * SSTR + kk + acol]);
#pragma unroll
            for (int jp = 0; jp < 2; ++jp)
                ldsm_x4(bf[jp], &Bb[(wn + jp * 16 + brow) * SSTR + kk + bcol]);
#pragma unroll
            for (int i = 0; i < 4; ++i)
#pragma unroll
                for (int j = 0; j < 4; ++j)
                    mma_tf32(d[i][j], af[i], &bf[j >> 1][(j & 1) * 2]);
        }
        __syncthreads();
        buf = (buf + 1 == 3) ? 0 : buf + 1;
    }

#pragma unroll
    for (int i = 0; i < 4; ++i) {
        int row = m0 + wm + i * 16 + g;
#pragma unroll
        for (int j = 0; j < 4; ++j) {
            int col = n0 + wn + j * 8 + c4 * 2;
            float b0 = 0.f, b1 = 0.f;
            if (BIAS) { b0 = bias[col]; b1 = bias[col + 1]; }
            *(float2*)(Cc + (size_t)row * Nn + col) =
                make_float2(d[i][j][0] + b0, d[i][j][1] + b1);
            *(float2*)(Cc + (size_t)(row + 8) * Nn + col) =
                make_float2(d[i][j][2] + b0, d[i][j][3] + b1);
        }
    }
}

// ---------------------------------------------------------------------------
// TF32 tensor-core flash attention, ldmatrix fragments, K/V reg prefetch.
// CTA = (b,h) x 128-query tile, 8 warps x 16 rows, 16 key-tiles of 64.
// ---------------------------------------------------------------------------
#define ASTR 68
#define ATTN_SMEM_WORDS (128 * ASTR * 2 + 64 * ASTR * 2)
#define ATTN_SMEM_BYTES (ATTN_SMEM_WORDS * 4)

__global__ __launch_bounds__(256)
void attn_kernel(const float* __restrict__ qkv, float* __restrict__ ao)
{
    extern __shared__ uint32_t smu[];
    uint32_t* Qs = smu;                        // [128][68]
    uint32_t* Ps = smu + 128 * ASTR;           // [128][68]
    uint32_t* Ks = smu + 256 * ASTR;           // [64][68]
    uint32_t* Vt = smu + 320 * ASTR;           // [64][68]

    const int tid  = threadIdx.x;
    const int lane = tid & 31;
    const int w    = tid >> 5;
    const int wm   = w * 16;
    const int g    = lane >> 2;
    const int c4   = lane & 3;
    const int bh   = blockIdx.x;
    const int b    = bh >> 4;
    const int h    = bh & 15;
    const int r0   = blockIdx.y * 128;
    const float scale = 0.125f;

    const int arow = (lane & 7) + (((lane >> 3) & 1) << 3);
    const int acol = ((lane >> 4) & 1) << 2;
    const int brow = ((lane >> 4) << 3) + (lane & 7);
    const int bcol = ((lane >> 3) & 1) << 2;

    // ---- load Q tile (pre-scaled, tf32) ----
    const float* qb = qkv + (size_t)b * N_ * QKV_COLS + h * HD_;
#pragma unroll
    for (int it = 0; it < 8; ++it) {
        int e  = tid + it * 256;
        int r  = e >> 4;
        int dd = (e & 15) << 2;
        float4 v = *(const float4*)(qb + (size_t)(r0 + r) * QKV_COLS + dd);
        uint4 t;
        t.x = f2tf32(v.x * scale); t.y = f2tf32(v.y * scale);
        t.z = f2tf32(v.z * scale); t.w = f2tf32(v.w * scale);
        *(uint4*)&Qs[r * ASTR + dd] = t;
    }

    // K/V prefetch registers
    float4 kreg[4];
    float  vreg[4][4];
    auto prefetch = [&](int t) {
#pragma unroll
        for (int it = 0; it < 4; ++it) {
            int e  = tid + it * 256;
            int m  = e >> 4;
            int dd = (e & 15) << 2;
            kreg[it] = *(const float4*)(qkv
                + (size_t)(b * N_ + t * 64 + m) * QKV_COLS + C_ + h * HD_ + dd);
        }
#pragma unroll
        for (int it = 0; it < 4; ++it) {
            int e  = tid + it * 256;
            int dd = e & 63;
            int m4 = (e >> 6) << 2;
            const float* vb = qkv
                + (size_t)(b * N_ + t * 64 + m4) * QKV_COLS + 2 * C_ + h * HD_ + dd;
            vreg[it][0] = vb[0];
            vreg[it][1] = vb[QKV_COLS];
            vreg[it][2] = vb[2 * QKV_COLS];
            vreg[it][3] = vb[3 * QKV_COLS];
        }
    };
    prefetch(0);

    float o[8][4];
    float m0r = -1e30f, m1r = -1e30f, l0 = 0.f, l1 = 0.f;
#pragma unroll
    for (int j = 0; j < 8; ++j)
#pragma unroll
        for (int r = 0; r < 4; ++r) o[j][r] = 0.f;

    for (int t = 0; t < 16; ++t) {
        __syncthreads();   // prior tile's K/V reads done

        // ---- store prefetched K [key][d] and V^T [d][key] ----
#pragma unroll
        for (int it = 0; it < 4; ++it) {
            int e  = tid + it * 256;
            int m  = e >> 4;
            int dd = (e & 15) << 2;
            uint4 tk;
            tk.x = f2tf32(kreg[it].x); tk.y = f2tf32(kreg[it].y);
            tk.z = f2tf32(kreg[it].z); tk.w = f2tf32(kreg[it].w);
            *(uint4*)&Ks[m * ASTR + dd] = tk;
        }
#pragma unroll
        for (int it = 0; it < 4; ++it) {
            int e  = tid + it * 256;
            int dd = e & 63;
            int m4 = (e >> 6) << 2;
            uint4 tv;
            tv.x = f2tf32(vreg[it][0]); tv.y = f2tf32(vreg[it][1]);
            tv.z = f2tf32(vreg[it][2]); tv.w = f2tf32(vreg[it][3]);
            *(uint4*)&Vt[dd * ASTR + m4] = tv;
        }
        __syncthreads();

        if (t + 1 < 16) prefetch(t + 1);   // overlaps with compute below

        // ---- S = (Q*scale) @ K^T ----
        float s[8][4];
#pragma unroll
        for (int j = 0; j < 8; ++j)
#pragma unroll
            for (int r = 0; r < 4; ++r) s[j][r] = 0.f;

#pragma unroll
        for (int kk = 0; kk < 64; kk += 8) {
            uint32_t a[4], bf[4][4];
            ldsm_x4(a, &Qs[(wm + arow) * ASTR + kk + acol]);
#pragma unroll
            for (int jp = 0; jp < 4; ++jp)
                ldsm_x4(bf[jp], &Ks[(jp * 16 + brow) * ASTR + kk + bcol]);
#pragma unroll
            for (int j = 0; j < 8; ++j)
                mma_tf32(s[j], a, &bf[j >> 1][(j & 1) * 2]);
        }

        // ---- online softmax on fragments ----
        float rm0 = -1e30f, rm1 = -1e30f;
#pragma unroll
        for (int j = 0; j < 8; ++j) {
            rm0 = fmaxf(rm0, fmaxf(s[j][0], s[j][1]));
            rm1 = fmaxf(rm1, fmaxf(s[j][2], s[j][3]));
        }
#pragma unroll
        for (int off = 1; off <= 2; off <<= 1) {
            rm0 = fmaxf(rm0, __shfl_xor_sync(0xffffffffu, rm0, off));
            rm1 = fmaxf(rm1, __shfl_xor_sync(0xffffffffu, rm1, off));
        }
        float mn0 = fmaxf(m0r, rm0), mn1 = fmaxf(m1r, rm1);
        float al0 = __expf(m0r - mn0), al1 = __expf(m1r - mn1);
        float rs0 = 0.f, rs1 = 0.f;
#pragma unroll
        for (int j = 0; j < 8; ++j) {
            s[j][0] = __expf(s[j][0] - mn0);
            s[j][1] = __expf(s[j][1] - mn0);
            s[j][2] = __expf(s[j][2] - mn1);
            s[j][3] = __expf(s[j][3] - mn1);
            rs0 += s[j][0] + s[j][1];
            rs1 += s[j][2] + s[j][3];
        }
#pragma unroll
        for (int off = 1; off <= 2; off <<= 1) {
            rs0 += __shfl_xor_sync(0xffffffffu, rs0, off);
            rs1 += __shfl_xor_sync(0xffffffffu, rs1, off);
        }
        l0 = l0 * al0 + rs0;  m0r = mn0;
        l1 = l1 * al1 + rs1;  m1r = mn1;
#pragma unroll
        for (int j = 0; j < 8; ++j) {
            o[j][0] *= al0; o[j][1] *= al0;
            o[j][2] *= al1; o[j][3] *= al1;
            uint2 p0 = make_uint2(f2tf32(s[j][0]), f2tf32(s[j][1]));
            uint2 p1 = make_uint2(f2tf32(s[j][2]), f2tf32(s[j][3]));
            *(uint2*)&Ps[(wm + g)     * ASTR + j * 8 + c4 * 2] = p0;
            *(uint2*)&Ps[(wm + g + 8) * ASTR + j * 8 + c4 * 2] = p1;
        }
        __syncwarp();   // P region is warp-private

        // ---- O += P @ V ----
#pragma unroll
        for (int kk = 0; kk < 64; kk += 8) {
            uint32_t a[4], bf[4][4];
            ldsm_x4(a, &Ps[(wm + arow) * ASTR + kk + acol]);
#pragma unroll
            for (int jp = 0; jp < 4; ++jp)
                ldsm_x4(bf[jp], &Vt[(jp * 16 + brow) * ASTR + kk + bcol]);
#pragma unroll
            for (int j = 0; j < 8; ++j)
                mma_tf32(o[j], a, &bf[j >> 1][(j & 1) * 2]);
        }
    }

    // ---- epilogue: (O / l), tf32-rounded, -> ao[b,n,h,hd] ----
    float inv0 = 1.f / l0, inv1 = 1.f / l1;
    int row0 = r0 + wm + g;
    float* aob = ao + (size_t)(b * N_) * C_ + h * HD_;
#pragma unroll
    for (int j = 0; j < 8; ++j) {
        int col = j * 8 + c4 * 2;
        float2 v0 = make_float2(__uint_as_float(f2tf32(o[j][0] * inv0)),
                                __uint_as_float(f2tf32(o[j][1] * inv0)));
        float2 v1 = make_float2(__uint_as_float(f2tf32(o[j][2] * inv1)),
                                __uint_as_float(f2tf32(o[j][3] * inv1)));
        *(float2*)(aob + (size_t)row0 * C_ + col) = v0;
        *(float2*)(aob + (size_t)(row0 + 8) * C_ + col) = v1;
    }
}

// ---------------------------------------------------------------------------
extern "C" void kernel_launch(void* const* d_in, const int* in_sizes, int n_in,
                              void* d_out, int out_size)
{
    const float* x      = (const float*)d_in[0];
    const float* w_qkv  = (const float*)d_in[1];
    const float* w_proj = (const float*)d_in[2];
    const float* b_proj = (const float*)d_in[3];
    float* out = (float*)d_out;

    float *qkv, *ao;
    uint32_t *xr, *wqr, *wpr;
    cudaGetSymbolAddress((void**)&qkv, g_qkv);
    cudaGetSymbolAddress((void**)&ao,  g_ao);
    cudaGetSymbolAddress((void**)&xr,  g_xr);
    cudaGetSymbolAddress((void**)&wqr, g_wqr);
    cudaGetSymbolAddress((void**)&wpr, g_wpr);

    // 0) Pre-round inputs to tf32 (RNA) once.
    round_tf32_kernel<<<(B_ * N_ * C_) / 1024, 256>>>(x, xr);
    round_tf32_kernel<<<(QKV_COLS * C_) / 1024, 256>>>(w_qkv, wqr);
    round_tf32_kernel<<<(C_ * C_) / 1024, 256>>>(w_proj, wpr);

    cudaFuncSetAttribute(tf32_gemm_db<false>,
                         cudaFuncAttributeMaxDynamicSharedMemorySize,
                         GEMM_SMEM_BYTES);
    cudaFuncSetAttribute(tf32_gemm_db<true>,
                         cudaFuncAttributeMaxDynamicSharedMemorySize,
                         GEMM_SMEM_BYTES);
    cudaFuncSetAttribute(attn_kernel,
                         cudaFuncAttributeMaxDynamicSharedMemorySize,
                         ATTN_SMEM_BYTES);

    // 1) QKV projection (3-stage cp.async TF32, ldmatrix fragments)
    tf32_gemm_db<false><<<dim3(QKV_COLS / 128, (B_ * N_) / 128), 256,
                          GEMM_SMEM_BYTES>>>(
        xr, wqr, nullptr, qkv, B_ * N_, QKV_COLS, C_);

    // 2) TF32 flash attention (writes tf32-rounded ao)
    attn_kernel<<<dim3(B_ * H_, N_ / 128), 256, ATTN_SMEM_BYTES>>>(qkv, ao);

    // 3) Output projection + bias
    tf32_gemm_db<true><<<dim3(C_ / 128, (B_ * N_) / 128), 256,
                         GEMM_SMEM_BYTES>>>(
        (const uint32_t*)ao, wpr, b_proj, out, B_ * N_, C_, C_);
}